// round 11
// baseline (speedup 1.0000x reference)
#include <cuda_runtime.h>
#include <cuda_bf16.h>
#include <math.h>
#include <stdint.h>

#define ND   1024
#define NH   16
#define HD   64
#define SEQ  2048
#define BATCH 4
#define MTOT (BATCH*SEQ)   // 8192

typedef __nv_bfloat16 bf16;

// ---------------- device-global scratch (allocation-free) -------------------
__device__ bf16 g_xhi[(size_t)MTOT*ND];
__device__ bf16 g_xlo[(size_t)MTOT*ND];
__device__ bf16 g_whi[4][(size_t)ND*ND];
__device__ bf16 g_wlo[4][(size_t)ND*ND];
__device__ bf16 g_qhi[(size_t)MTOT*ND];
__device__ bf16 g_qlo[(size_t)MTOT*ND];
__device__ bf16 g_khi[(size_t)MTOT*ND];
__device__ bf16 g_klo[(size_t)MTOT*ND];
__device__ bf16 g_vhi[(size_t)MTOT*ND];
__device__ bf16 g_vlo[(size_t)MTOT*ND];
__device__ bf16 g_ohi[(size_t)MTOT*ND];
__device__ bf16 g_olo[(size_t)MTOT*ND];

// ---------------- PTX helpers (baseline ISA only) ---------------------------
__device__ __forceinline__ uint32_t smem_u32(const void* p) {
    uint32_t a;
    asm("{ .reg .u64 t; cvta.to.shared.u64 t, %1; cvt.u32.u64 %0, t; }"
        : "=r"(a) : "l"(p));
    return a;
}
__device__ __forceinline__ void ldsm4(uint32_t* r, uint32_t addr) {
    asm volatile("ldmatrix.sync.aligned.m8n8.x4.shared.b16 {%0,%1,%2,%3}, [%4];"
                 : "=r"(r[0]), "=r"(r[1]), "=r"(r[2]), "=r"(r[3]) : "r"(addr));
}
__device__ __forceinline__ void ldsm4t(uint32_t* r, uint32_t addr) {
    asm volatile("ldmatrix.sync.aligned.m8n8.x4.trans.shared.b16 {%0,%1,%2,%3}, [%4];"
                 : "=r"(r[0]), "=r"(r[1]), "=r"(r[2]), "=r"(r[3]) : "r"(addr));
}
__device__ __forceinline__ void mma_bf16(float* c, const uint32_t* a,
                                         const uint32_t* b) {
    asm volatile(
        "mma.sync.aligned.m16n8k16.row.col.f32.bf16.bf16.f32 "
        "{%0,%1,%2,%3}, {%4,%5,%6,%7}, {%8,%9}, {%0,%1,%2,%3};"
        : "+f"(c[0]), "+f"(c[1]), "+f"(c[2]), "+f"(c[3])
        : "r"(a[0]), "r"(a[1]), "r"(a[2]), "r"(a[3]), "r"(b[0]), "r"(b[1]));
}
__device__ __forceinline__ void cp16(uint32_t saddr, const void* g) {
    asm volatile("cp.async.cg.shared.global [%0], [%1], 16;"
                 :: "r"(saddr), "l"(g) : "memory");
}
__device__ __forceinline__ void cp_commit() {
    asm volatile("cp.async.commit_group;" ::: "memory");
}
template<int N>
__device__ __forceinline__ void cp_wait() {
    asm volatile("cp.async.wait_group %0;" :: "n"(N) : "memory");
}
__device__ __forceinline__ uint32_t pk2(float lo, float hi) {
    uint32_t r;
    asm("cvt.rn.bf16x2.f32 %0, %1, %2;" : "=r"(r) : "f"(hi), "f"(lo));
    return r;
}
__device__ __forceinline__ float bfl(uint32_t u) { return __uint_as_float(u << 16); }
__device__ __forceinline__ float bfh(uint32_t u) { return __uint_as_float(u & 0xffff0000u); }

// ---------------------------------------------------------------------------
// fp32 -> (bf16 hi, bf16 lo) splits
// ---------------------------------------------------------------------------
__global__ __launch_bounds__(256) void split_f32(
    const float* __restrict__ src, bf16* __restrict__ hi,
    bf16* __restrict__ lo, int n4)
{
    int i = blockIdx.x * blockDim.x + threadIdx.x;
    if (i >= n4) return;
    float4 v = *(const float4*)(src + (size_t)i * 4);
    float vs[4] = {v.x, v.y, v.z, v.w};
    uint32_t h[2], l[2];
    #pragma unroll
    for (int j = 0; j < 2; j++) {
        h[j] = pk2(vs[2*j], vs[2*j+1]);
        l[j] = pk2(vs[2*j] - bfl(h[j]), vs[2*j+1] - bfh(h[j]));
    }
    *(uint2*)(hi + (size_t)i * 4) = make_uint2(h[0], h[1]);
    *(uint2*)(lo + (size_t)i * 4) = make_uint2(l[0], l[1]);
}

__global__ __launch_bounds__(256) void split_w4(
    const float* __restrict__ W0, const float* __restrict__ W1,
    const float* __restrict__ W2, const float* __restrict__ W3,
    bf16* __restrict__ hi_base, bf16* __restrict__ lo_base)
{
    const int w = blockIdx.y;
    const float* src = (w == 0) ? W0 : (w == 1) ? W1 : (w == 2) ? W2 : W3;
    const size_t WSZ = (size_t)ND * ND;
    bf16* hi = hi_base + (size_t)w * WSZ;
    bf16* lo = lo_base + (size_t)w * WSZ;
    int i = blockIdx.x * blockDim.x + threadIdx.x;
    if (i >= (int)(WSZ / 4)) return;
    float4 v = *(const float4*)(src + (size_t)i * 4);
    float vs[4] = {v.x, v.y, v.z, v.w};
    uint32_t h[2], l[2];
    #pragma unroll
    for (int j = 0; j < 2; j++) {
        h[j] = pk2(vs[2*j], vs[2*j+1]);
        l[j] = pk2(vs[2*j] - bfl(h[j]), vs[2*j+1] - bfh(h[j]));
    }
    *(uint2*)(hi + (size_t)i * 4) = make_uint2(h[0], h[1]);
    *(uint2*)(lo + (size_t)i * 4) = make_uint2(l[0], l[1]);
}

// ---------------------------------------------------------------------------
// HMMA 3xBF16 GEMM core, 2-stage cp.async pipeline, ONE barrier per K-block.
// C = (Ahi+Alo)@(Bhi+Blo)^T + bias.  128x128 CTA, BK=32, 8 warps (2x4).
// ---------------------------------------------------------------------------
#define SMS 40
#define G_TILE (128*SMS)
#define G_STG  (4*G_TILE)

template<int OUTMODE>
__device__ __forceinline__ void gemm_core(
    const bf16* __restrict__ Ahi, const bf16* __restrict__ Alo,
    const bf16* __restrict__ Bhi, const bf16* __restrict__ Blo,
    const float* __restrict__ bias, float* __restrict__ C,
    bf16* __restrict__ Chi, bf16* __restrict__ Clo,
    int m0, int n0)
{
    extern __shared__ bf16 gsm[];
    const uint32_t smB = smem_u32(gsm);

    const int tid  = threadIdx.x;
    const int lane = tid & 31, wid = tid >> 5;
    const int wm = (wid >> 2) << 6;
    const int wn = (wid & 3) << 5;

    float acc[4][4][4] = {};

    const int a_row  = lane & 15;
    const int a_koff = (lane >> 4) << 3;
    const int b_row  = ((lane >> 4) << 3) + (lane & 7);
    const int b_koff = ((lane >> 3) & 1) << 3;

    const int lr = tid >> 2, lc = (tid & 3) << 3;
    const uint32_t so0 = (uint32_t)(lr*SMS + lc) * 2;
    const uint32_t so1 = (uint32_t)((lr+64)*SMS + lc) * 2;

    auto load_stage = [&](int stage, int kb) {
        const int k0 = kb << 5;
        const uint32_t sb = smB + (uint32_t)stage * G_STG * 2;
        const size_t ga0 = (size_t)(m0 + lr) * ND + k0 + lc;
        const size_t ga1 = (size_t)(m0 + lr + 64) * ND + k0 + lc;
        const size_t gb0 = (size_t)(n0 + lr) * ND + k0 + lc;
        const size_t gb1 = (size_t)(n0 + lr + 64) * ND + k0 + lc;
        cp16(sb + 0*G_TILE*2 + so0, Ahi + ga0);
        cp16(sb + 0*G_TILE*2 + so1, Ahi + ga1);
        cp16(sb + 1*G_TILE*2 + so0, Alo + ga0);
        cp16(sb + 1*G_TILE*2 + so1, Alo + ga1);
        cp16(sb + 2*G_TILE*2 + so0, Bhi + gb0);
        cp16(sb + 2*G_TILE*2 + so1, Bhi + gb1);
        cp16(sb + 3*G_TILE*2 + so0, Blo + gb0);
        cp16(sb + 3*G_TILE*2 + so1, Blo + gb1);
        cp_commit();
    };

    load_stage(0, 0);

    for (int kb = 0; kb < 32; kb++) {
        cp_wait<0>();
        __syncthreads();     // stage kb visible; all warps done reading (kb-1)&1
        if (kb + 1 < 32) load_stage((kb + 1) & 1, kb + 1);

        const uint32_t sb = smB + (uint32_t)(kb & 1) * G_STG * 2;
        const uint32_t sAhiB = sb, sAloB = sb + G_TILE*2;
        const uint32_t sBhiB = sb + 2*G_TILE*2, sBloB = sb + 3*G_TILE*2;

        #pragma unroll
        for (int ks = 0; ks < 2; ks++) {
            const int kk = ks << 4;
            uint32_t ah[4][4], al[4][4], bh[4][2], bl[4][2];
            #pragma unroll
            for (int mi = 0; mi < 4; mi++) {
                const uint32_t off =
                    (uint32_t)(((wm + (mi<<4) + a_row)*SMS + kk + a_koff) * 2);
                ldsm4(ah[mi], sAhiB + off);
                ldsm4(al[mi], sAloB + off);
            }
            #pragma unroll
            for (int nj = 0; nj < 2; nj++) {
                const uint32_t off =
                    (uint32_t)(((wn + (nj<<4) + b_row)*SMS + kk + b_koff) * 2);
                uint32_t r4[4];
                ldsm4(r4, sBhiB + off);
                bh[nj*2][0]=r4[0]; bh[nj*2][1]=r4[1];
                bh[nj*2+1][0]=r4[2]; bh[nj*2+1][1]=r4[3];
                ldsm4(r4, sBloB + off);
                bl[nj*2][0]=r4[0]; bl[nj*2][1]=r4[1];
                bl[nj*2+1][0]=r4[2]; bl[nj*2+1][1]=r4[3];
            }
            #pragma unroll
            for (int mi = 0; mi < 4; mi++)
                #pragma unroll
                for (int ni = 0; ni < 4; ni++) {
                    mma_bf16(acc[mi][ni], ah[mi], bh[ni]);
                    mma_bf16(acc[mi][ni], ah[mi], bl[ni]);
                    mma_bf16(acc[mi][ni], al[mi], bh[ni]);
                }
        }
    }

    const int er = lane >> 2, ec = (lane & 3) << 1;
    #pragma unroll
    for (int ni = 0; ni < 4; ni++) {
        const int col = n0 + wn + (ni << 3) + ec;
        const float b0 = __ldg(bias + col), b1 = __ldg(bias + col + 1);
        #pragma unroll
        for (int mi = 0; mi < 4; mi++) {
            const int row = m0 + wm + (mi << 4) + er;
            const float v0 = acc[mi][ni][0] + b0, v1 = acc[mi][ni][1] + b1;
            const float v2 = acc[mi][ni][2] + b0, v3 = acc[mi][ni][3] + b1;
            if (OUTMODE == 0) {
                *(float2*)(C + (size_t)row * ND + col)       = make_float2(v0, v1);
                *(float2*)(C + (size_t)(row + 8) * ND + col) = make_float2(v2, v3);
            } else {
                uint32_t h0 = pk2(v0, v1);
                uint32_t l0 = pk2(v0 - bfl(h0), v1 - bfh(h0));
                uint32_t h1 = pk2(v2, v3);
                uint32_t l1 = pk2(v2 - bfl(h1), v3 - bfh(h1));
                *(uint32_t*)(Chi + (size_t)row * ND + col)       = h0;
                *(uint32_t*)(Clo + (size_t)row * ND + col)       = l0;
                *(uint32_t*)(Chi + (size_t)(row + 8) * ND + col) = h1;
                *(uint32_t*)(Clo + (size_t)(row + 8) * ND + col) = l1;
            }
        }
    }
}

__global__ __launch_bounds__(256, 2) void gemm_qkv(
    const bf16* __restrict__ Ahi, const bf16* __restrict__ Alo,
    const bf16* __restrict__ Whi_base, const bf16* __restrict__ Wlo_base,
    const float* __restrict__ bq, const float* __restrict__ bk,
    const float* __restrict__ bv,
    bf16* __restrict__ qhi, bf16* __restrict__ qlo,
    bf16* __restrict__ khi, bf16* __restrict__ klo,
    bf16* __restrict__ vhi, bf16* __restrict__ vlo)
{
    const int z = blockIdx.z;
    const size_t WSZ = (size_t)ND * ND;
    const bf16* Bhi = Whi_base + (size_t)z * WSZ;
    const bf16* Blo = Wlo_base + (size_t)z * WSZ;
    const float* bias = (z == 0) ? bq : (z == 1) ? bk : bv;
    bf16* Chi = (z == 0) ? qhi : (z == 1) ? khi : vhi;
    bf16* Clo = (z == 0) ? qlo : (z == 1) ? klo : vlo;
    gemm_core<1>(Ahi, Alo, Bhi, Blo, bias, nullptr, Chi, Clo,
                 blockIdx.y << 7, blockIdx.x << 7);
}

__global__ __launch_bounds__(256, 2) void gemm_proj(
    const bf16* __restrict__ Ahi, const bf16* __restrict__ Alo,
    const bf16* __restrict__ Bhi, const bf16* __restrict__ Blo,
    const float* __restrict__ bias, float* __restrict__ C)
{
    gemm_core<0>(Ahi, Alo, Bhi, Blo, bias, C, nullptr, nullptr,
                 blockIdx.y << 7, blockIdx.x << 7);
}

// ---------------------------------------------------------------------------
// Tensor-core flash attention, 2-stage cp.async, cross-tile S pipelining:
// S(kt+1) is computed (into the alternate score buffer) adjacent to
// softmax(kt) so the tensor pipe stays busy through the softmax latency.
// Grid: (qtile=16, hb=64).  8 warps; warp = 16 query rows; K tile = 64 keys.
// ---------------------------------------------------------------------------
#define APAD 72
#define A_TILE (64*APAD)
#define A_STG  (4*A_TILE)

__global__ __launch_bounds__(256) void attn_mma(
    const bf16* __restrict__ Qhi, const bf16* __restrict__ Qlo,
    const bf16* __restrict__ Khi, const bf16* __restrict__ Klo,
    const bf16* __restrict__ Vhi, const bf16* __restrict__ Vlo,
    bf16* __restrict__ Ohi, bf16* __restrict__ Olo)
{
    extern __shared__ bf16 sm[];
    bf16* sQh = sm;                   // 128 x APAD
    bf16* sQl = sQh + 128*APAD;
    bf16* sKV = sQl + 128*APAD;       // 2 stages x (Kh,Kl,Vh,Vl) 64 x APAD

    const int tid = threadIdx.x;
    const int lane = tid & 31, wid = tid >> 5;
    const int hb = blockIdx.y;
    const int b  = hb & 3, h = hb >> 2;
    const int q0 = blockIdx.x << 7;
    const size_t base = (size_t)b * SEQ * ND + h * HD;

    const uint32_t sKVB = smem_u32(sKV);
    const uint32_t sQlB = smem_u32(sQl);

    const int kr0 = tid >> 3, kc = (tid & 7) << 3;
    const uint32_t kso0 = (uint32_t)(kr0*APAD + kc) * 2;
    const uint32_t kso1 = (uint32_t)((kr0+32)*APAD + kc) * 2;

    auto load_kv = [&](int stage, int k0) {
        const uint32_t sb = sKVB + (uint32_t)stage * A_STG * 2;
        const size_t g0 = base + (size_t)(k0 + kr0) * ND + kc;
        const size_t g1 = base + (size_t)(k0 + kr0 + 32) * ND + kc;
        cp16(sb + 0*A_TILE*2 + kso0, Khi + g0);
        cp16(sb + 0*A_TILE*2 + kso1, Khi + g1);
        cp16(sb + 1*A_TILE*2 + kso0, Klo + g0);
        cp16(sb + 1*A_TILE*2 + kso1, Klo + g1);
        cp16(sb + 2*A_TILE*2 + kso0, Vhi + g0);
        cp16(sb + 2*A_TILE*2 + kso1, Vhi + g1);
        cp16(sb + 3*A_TILE*2 + kso0, Vlo + g0);
        cp16(sb + 3*A_TILE*2 + kso1, Vlo + g1);
        cp_commit();
    };

    // --- load Q tile + prefetch KV stages 0 and 1 ---
    for (int i = tid; i < 128*8; i += 256) {
        const int r = i >> 3, c8 = (i & 7) << 3;
        const size_t g = base + (size_t)(q0 + r) * ND + c8;
        *(int4*)&sQh[r*APAD + c8] = *(const int4*)(Qhi + g);
        *(int4*)&sQl[r*APAD + c8] = *(const int4*)(Qlo + g);
    }
    load_kv(0, 0);
    load_kv(1, 64);
    __syncthreads();   // Q visible

    // --- Q hi fragments resident; Q lo reloaded per tile (register relief) ---
    const int a_row  = lane & 15;
    const int a_koff = (lane >> 4) << 3;
    uint32_t qh[4][4];
    #pragma unroll
    for (int ks = 0; ks < 4; ks++) {
        const uint32_t off =
            (uint32_t)(((wid*16 + a_row)*APAD + ks*16 + a_koff) * 2);
        ldsm4(qh[ks], smem_u32(sQh) + off);
    }
    const uint32_t ql_off0 =
        (uint32_t)(((wid*16 + a_row)*APAD + a_koff) * 2);

    const int b_row  = ((lane >> 4) << 3) + (lane & 7);
    const int b_koff = ((lane >> 3) & 1) << 3;
    const int v_krow = (((lane >> 3) & 1) << 3) + (lane & 7);
    const int v_doff = (lane >> 4) << 3;

    float m0v = -1e30f, m1v = -1e30f, l0v = 0.f, l1v = 0.f;
    float o[8][4] = {};

    // S = Q K^T into a score buffer (3-term split; Q-lo reloaded from smem)
    auto compute_S = [&](float (&s)[8][4], int stage) {
        const uint32_t sb = sKVB + (uint32_t)stage * A_STG * 2;
        const uint32_t sKhB = sb, sKlB = sb + A_TILE*2;
        #pragma unroll
        for (int f = 0; f < 8; f++)
            #pragma unroll
            for (int j = 0; j < 4; j++) s[f][j] = 0.f;
        #pragma unroll
        for (int ks = 0; ks < 4; ks++) {
            uint32_t ql[4];
            ldsm4(ql, sQlB + ql_off0 + (uint32_t)(ks*16*2));
            #pragma unroll
            for (int ng = 0; ng < 4; ng++) {
                const uint32_t off =
                    (uint32_t)(((ng*16 + b_row)*APAD + ks*16 + b_koff) * 2);
                uint32_t kbh[4], kbl[4];
                ldsm4(kbh, sKhB + off);
                ldsm4(kbl, sKlB + off);
                mma_bf16(s[ng*2],   qh[ks], kbh);
                mma_bf16(s[ng*2+1], qh[ks], kbh + 2);
                mma_bf16(s[ng*2],   qh[ks], kbl);
                mma_bf16(s[ng*2+1], qh[ks], kbl + 2);
                mma_bf16(s[ng*2],   ql,     kbh);
                mma_bf16(s[ng*2+1], ql,     kbh + 2);
            }
        }
    };

    // softmax + pack + O += P V  (consumes score buffer, reads V of 'stage')
    auto softmax_pv = [&](float (&s)[8][4], int stage) {
        const uint32_t sb = sKVB + (uint32_t)stage * A_STG * 2;
        const uint32_t sVhB = sb + 2*A_TILE*2, sVlB = sb + 3*A_TILE*2;

        float mx0 = m0v, mx1 = m1v;
        #pragma unroll
        for (int f = 0; f < 8; f++) {
            mx0 = fmaxf(mx0, fmaxf(s[f][0], s[f][1]));
            mx1 = fmaxf(mx1, fmaxf(s[f][2], s[f][3]));
        }
        mx0 = fmaxf(mx0, __shfl_xor_sync(0xffffffffu, mx0, 1));
        mx0 = fmaxf(mx0, __shfl_xor_sync(0xffffffffu, mx0, 2));
        mx1 = fmaxf(mx1, __shfl_xor_sync(0xffffffffu, mx1, 1));
        mx1 = fmaxf(mx1, __shfl_xor_sync(0xffffffffu, mx1, 2));
        const float sc0 = __expf(m0v - mx0);
        const float sc1 = __expf(m1v - mx1);
        float sum0 = 0.f, sum1 = 0.f;
        #pragma unroll
        for (int f = 0; f < 8; f++) {
            s[f][0] = __expf(s[f][0] - mx0);
            s[f][1] = __expf(s[f][1] - mx0);
            s[f][2] = __expf(s[f][2] - mx1);
            s[f][3] = __expf(s[f][3] - mx1);
            sum0 += s[f][0] + s[f][1];
            sum1 += s[f][2] + s[f][3];
        }
        sum0 += __shfl_xor_sync(0xffffffffu, sum0, 1);
        sum0 += __shfl_xor_sync(0xffffffffu, sum0, 2);
        sum1 += __shfl_xor_sync(0xffffffffu, sum1, 1);
        sum1 += __shfl_xor_sync(0xffffffffu, sum1, 2);
        l0v = l0v * sc0 + sum0;  m0v = mx0;
        l1v = l1v * sc1 + sum1;  m1v = mx1;
        #pragma unroll
        for (int f = 0; f < 8; f++) {
            o[f][0] *= sc0; o[f][1] *= sc0;
            o[f][2] *= sc1; o[f][3] *= sc1;
        }

        uint32_t ph[4][4], pl[4][4];
        #pragma unroll
        for (int ksp = 0; ksp < 4; ksp++) {
            const float* e = s[2*ksp];
            const float* oq = s[2*ksp+1];
            ph[ksp][0] = pk2(e[0], e[1]);
            pl[ksp][0] = pk2(e[0] - bfl(ph[ksp][0]), e[1] - bfh(ph[ksp][0]));
            ph[ksp][1] = pk2(e[2], e[3]);
            pl[ksp][1] = pk2(e[2] - bfl(ph[ksp][1]), e[3] - bfh(ph[ksp][1]));
            ph[ksp][2] = pk2(oq[0], oq[1]);
            pl[ksp][2] = pk2(oq[0] - bfl(ph[ksp][2]), oq[1] - bfh(ph[ksp][2]));
            ph[ksp][3] = pk2(oq[2], oq[3]);
            pl[ksp][3] = pk2(oq[2] - bfl(ph[ksp][3]), oq[3] - bfh(ph[ksp][3]));
        }

        #pragma unroll
        for (int ksp = 0; ksp < 4; ksp++) {
            #pragma unroll
            for (int dg = 0; dg < 4; dg++) {
                const uint32_t off =
                    (uint32_t)(((ksp*16 + v_krow)*APAD + dg*16 + v_doff) * 2);
                uint32_t vbh[4], vbl[4];
                ldsm4t(vbh, sVhB + off);
                ldsm4t(vbl, sVlB + off);
                mma_bf16(o[dg*2],   ph[ksp], vbh);
                mma_bf16(o[dg*2+1], ph[ksp], vbh + 2);
                mma_bf16(o[dg*2],   ph[ksp], vbl);
                mma_bf16(o[dg*2+1], ph[ksp], vbl + 2);
                mma_bf16(o[dg*2],   pl[ksp], vbh);
                mma_bf16(o[dg*2+1], pl[ksp], vbh + 2);
            }
        }
    };

    float sA[8][4], sB[8][4];

    cp_wait<1>();        // stage 0 landed (stage-1 group still pending)
    __syncthreads();
    compute_S(sA, 0);    // S(0)

    for (int kt = 0; kt < 32; kt += 2) {
        // ---- tile kt (even): scores in sA, V in stage 0 ----
        cp_wait<0>();            // KV(kt+1) landed
        __syncthreads();         // visible to all; all warps past prior reads
        compute_S(sB, 1);        // S(kt+1)  — overlaps softmax below
        softmax_pv(sA, 0);       // softmax(kt) + PV(kt)
        __syncthreads();         // all warps done reading stage 0
        if (kt + 2 < 32) load_kv(0, (kt + 2) << 6);

        // ---- tile kt+1 (odd): scores in sB, V in stage 1 ----
        if (kt + 2 < 32) {
            cp_wait<0>();        // KV(kt+2) landed
            __syncthreads();
            compute_S(sA, 0);    // S(kt+2)
        }
        softmax_pv(sB, 1);
        __syncthreads();
        if (kt + 3 < 32) load_kv(1, (kt + 3) << 6);
    }

    // --- normalize + write hi/lo bf16 output ---
    const float inv0 = 1.0f / l0v, inv1 = 1.0f / l1v;
    const int r0 = q0 + wid*16 + (lane >> 2);
    const int ec = (lane & 3) << 1;
    #pragma unroll
    for (int dg = 0; dg < 8; dg++) {
        const int col = dg*8 + ec;
        const size_t g0 = base + (size_t)r0 * ND + col;
        const size_t g1 = base + (size_t)(r0 + 8) * ND + col;
        const float v0 = o[dg][0]*inv0, v1 = o[dg][1]*inv0;
        const float v2 = o[dg][2]*inv1, v3 = o[dg][3]*inv1;
        uint32_t h0 = pk2(v0, v1);
        uint32_t l0 = pk2(v0 - bfl(h0), v1 - bfh(h0));
        uint32_t h1 = pk2(v2, v3);
        uint32_t l1 = pk2(v2 - bfl(h1), v3 - bfh(h1));
        *(uint32_t*)(Ohi + g0) = h0;
        *(uint32_t*)(Olo + g0) = l0;
        *(uint32_t*)(Ohi + g1) = h1;
        *(uint32_t*)(Olo + g1) = l1;
    }
}

// ---------------------------------------------------------------------------
extern "C" void kernel_launch(void* const* d_in, const int* in_sizes, int n_in,
                              void* d_out, int out_size)
{
    const float* x  = (const float*)d_in[0];
    const float* Wq = (const float*)d_in[1];
    const float* bq = (const float*)d_in[2];
    const float* Wk = (const float*)d_in[3];
    const float* bk = (const float*)d_in[4];
    const float* Wv = (const float*)d_in[5];
    const float* bv = (const float*)d_in[6];
    const float* Wp = (const float*)d_in[7];
    const float* bp = (const float*)d_in[8];
    float* out = (float*)d_out;

    bf16 *xhi, *xlo, *whi, *wlo;
    bf16 *qhi, *qlo, *khi, *klo, *vhi, *vlo, *ohi, *olo;
    cudaGetSymbolAddress((void**)&xhi, g_xhi);
    cudaGetSymbolAddress((void**)&xlo, g_xlo);
    cudaGetSymbolAddress((void**)&whi, g_whi);
    cudaGetSymbolAddress((void**)&wlo, g_wlo);
    cudaGetSymbolAddress((void**)&qhi, g_qhi);
    cudaGetSymbolAddress((void**)&qlo, g_qlo);
    cudaGetSymbolAddress((void**)&khi, g_khi);
    cudaGetSymbolAddress((void**)&klo, g_klo);
    cudaGetSymbolAddress((void**)&vhi, g_vhi);
    cudaGetSymbolAddress((void**)&vlo, g_vlo);
    cudaGetSymbolAddress((void**)&ohi, g_ohi);
    cudaGetSymbolAddress((void**)&olo, g_olo);

    const size_t WSZ = (size_t)ND * ND;

    split_f32<<<(MTOT*ND/4 + 255)/256, 256>>>(x, xhi, xlo, MTOT*ND/4);
    split_w4<<<dim3((ND*ND/4 + 255)/256, 4), 256>>>(Wq, Wk, Wv, Wp, whi, wlo);

    const int gemm_smem = 2 * G_STG * (int)sizeof(bf16);   // 81,920 B
    cudaFuncSetAttribute(gemm_qkv, cudaFuncAttributeMaxDynamicSharedMemorySize,
                         gemm_smem);
    cudaFuncSetAttribute(gemm_proj, cudaFuncAttributeMaxDynamicSharedMemorySize,
                         gemm_smem);

    gemm_qkv<<<dim3(ND/128, MTOT/128, 3), 256, gemm_smem>>>(
        xhi, xlo, whi, wlo, bq, bk, bv,
        qhi, qlo, khi, klo, vhi, vlo);

    const int attn_smem = (2*128*APAD + 2*A_STG) * (int)sizeof(bf16);  // 110,592 B
    cudaFuncSetAttribute(attn_mma,
                         cudaFuncAttributeMaxDynamicSharedMemorySize, attn_smem);
    attn_mma<<<dim3(SEQ/128, NH*BATCH), 256, attn_smem>>>(
        qhi, qlo, khi, klo, vhi, vlo, ohi, olo);

    gemm_proj<<<dim3(ND/128, MTOT/128), 256, gemm_smem>>>(
        ohi, olo, whi + 3*WSZ, wlo + 3*WSZ, bp, out);
}

// round 12
// speedup vs baseline: 1.1332x; 1.1332x over previous
#include <cuda_runtime.h>
#include <cuda_bf16.h>
#include <math.h>
#include <stdint.h>

#define ND   1024
#define NH   16
#define HD   64
#define SEQ  2048
#define BATCH 4
#define MTOT (BATCH*SEQ)   // 8192

typedef __nv_bfloat16 bf16;

// ---------------- device-global scratch (allocation-free) -------------------
__device__ bf16 g_xhi[(size_t)MTOT*ND];
__device__ bf16 g_xlo[(size_t)MTOT*ND];
__device__ bf16 g_whi[4][(size_t)ND*ND];
__device__ bf16 g_wlo[4][(size_t)ND*ND];
__device__ bf16 g_qhi[(size_t)MTOT*ND];
__device__ bf16 g_qlo[(size_t)MTOT*ND];
__device__ bf16 g_khi[(size_t)MTOT*ND];
__device__ bf16 g_klo[(size_t)MTOT*ND];
__device__ bf16 g_vhi[(size_t)MTOT*ND];
__device__ bf16 g_vlo[(size_t)MTOT*ND];
__device__ bf16 g_ohi[(size_t)MTOT*ND];
__device__ bf16 g_olo[(size_t)MTOT*ND];

// ---------------- PTX helpers (baseline ISA only) ---------------------------
__device__ __forceinline__ uint32_t smem_u32(const void* p) {
    uint32_t a;
    asm("{ .reg .u64 t; cvta.to.shared.u64 t, %1; cvt.u32.u64 %0, t; }"
        : "=r"(a) : "l"(p));
    return a;
}
__device__ __forceinline__ void ldsm4(uint32_t* r, uint32_t addr) {
    asm volatile("ldmatrix.sync.aligned.m8n8.x4.shared.b16 {%0,%1,%2,%3}, [%4];"
                 : "=r"(r[0]), "=r"(r[1]), "=r"(r[2]), "=r"(r[3]) : "r"(addr));
}
__device__ __forceinline__ void ldsm4t(uint32_t* r, uint32_t addr) {
    asm volatile("ldmatrix.sync.aligned.m8n8.x4.trans.shared.b16 {%0,%1,%2,%3}, [%4];"
                 : "=r"(r[0]), "=r"(r[1]), "=r"(r[2]), "=r"(r[3]) : "r"(addr));
}
__device__ __forceinline__ void mma_bf16(float* c, const uint32_t* a,
                                         const uint32_t* b) {
    asm volatile(
        "mma.sync.aligned.m16n8k16.row.col.f32.bf16.bf16.f32 "
        "{%0,%1,%2,%3}, {%4,%5,%6,%7}, {%8,%9}, {%0,%1,%2,%3};"
        : "+f"(c[0]), "+f"(c[1]), "+f"(c[2]), "+f"(c[3])
        : "r"(a[0]), "r"(a[1]), "r"(a[2]), "r"(a[3]), "r"(b[0]), "r"(b[1]));
}
__device__ __forceinline__ void cp16(uint32_t saddr, const void* g) {
    asm volatile("cp.async.cg.shared.global [%0], [%1], 16;"
                 :: "r"(saddr), "l"(g) : "memory");
}
__device__ __forceinline__ void cp_commit() {
    asm volatile("cp.async.commit_group;" ::: "memory");
}
template<int N>
__device__ __forceinline__ void cp_wait() {
    asm volatile("cp.async.wait_group %0;" :: "n"(N) : "memory");
}
__device__ __forceinline__ uint32_t pk2(float lo, float hi) {
    uint32_t r;
    asm("cvt.rn.bf16x2.f32 %0, %1, %2;" : "=r"(r) : "f"(hi), "f"(lo));
    return r;
}
__device__ __forceinline__ float bfl(uint32_t u) { return __uint_as_float(u << 16); }
__device__ __forceinline__ float bfh(uint32_t u) { return __uint_as_float(u & 0xffff0000u); }

// ---------------------------------------------------------------------------
// fp32 -> (bf16 hi, bf16 lo) splits
// ---------------------------------------------------------------------------
__global__ __launch_bounds__(256) void split_f32(
    const float* __restrict__ src, bf16* __restrict__ hi,
    bf16* __restrict__ lo, int n4)
{
    int i = blockIdx.x * blockDim.x + threadIdx.x;
    if (i >= n4) return;
    float4 v = *(const float4*)(src + (size_t)i * 4);
    float vs[4] = {v.x, v.y, v.z, v.w};
    uint32_t h[2], l[2];
    #pragma unroll
    for (int j = 0; j < 2; j++) {
        h[j] = pk2(vs[2*j], vs[2*j+1]);
        l[j] = pk2(vs[2*j] - bfl(h[j]), vs[2*j+1] - bfh(h[j]));
    }
    *(uint2*)(hi + (size_t)i * 4) = make_uint2(h[0], h[1]);
    *(uint2*)(lo + (size_t)i * 4) = make_uint2(l[0], l[1]);
}

__global__ __launch_bounds__(256) void split_w4(
    const float* __restrict__ W0, const float* __restrict__ W1,
    const float* __restrict__ W2, const float* __restrict__ W3,
    bf16* __restrict__ hi_base, bf16* __restrict__ lo_base)
{
    const int w = blockIdx.y;
    const float* src = (w == 0) ? W0 : (w == 1) ? W1 : (w == 2) ? W2 : W3;
    const size_t WSZ = (size_t)ND * ND;
    bf16* hi = hi_base + (size_t)w * WSZ;
    bf16* lo = lo_base + (size_t)w * WSZ;
    int i = blockIdx.x * blockDim.x + threadIdx.x;
    if (i >= (int)(WSZ / 4)) return;
    float4 v = *(const float4*)(src + (size_t)i * 4);
    float vs[4] = {v.x, v.y, v.z, v.w};
    uint32_t h[2], l[2];
    #pragma unroll
    for (int j = 0; j < 2; j++) {
        h[j] = pk2(vs[2*j], vs[2*j+1]);
        l[j] = pk2(vs[2*j] - bfl(h[j]), vs[2*j+1] - bfh(h[j]));
    }
    *(uint2*)(hi + (size_t)i * 4) = make_uint2(h[0], h[1]);
    *(uint2*)(lo + (size_t)i * 4) = make_uint2(l[0], l[1]);
}

// ---------------------------------------------------------------------------
// HMMA 3xBF16 GEMM core, 2-stage cp.async pipeline, ONE barrier per K-block.
// C = (Ahi+Alo)@(Bhi+Blo)^T + bias.  128x128 CTA, BK=32, 8 warps (2x4).
// ---------------------------------------------------------------------------
#define SMS 40
#define G_TILE (128*SMS)
#define G_STG  (4*G_TILE)

template<int OUTMODE>
__device__ __forceinline__ void gemm_core(
    const bf16* __restrict__ Ahi, const bf16* __restrict__ Alo,
    const bf16* __restrict__ Bhi, const bf16* __restrict__ Blo,
    const float* __restrict__ bias, float* __restrict__ C,
    bf16* __restrict__ Chi, bf16* __restrict__ Clo,
    int m0, int n0)
{
    extern __shared__ bf16 gsm[];
    const uint32_t smB = smem_u32(gsm);

    const int tid  = threadIdx.x;
    const int lane = tid & 31, wid = tid >> 5;
    const int wm = (wid >> 2) << 6;
    const int wn = (wid & 3) << 5;

    float acc[4][4][4] = {};

    const int a_row  = lane & 15;
    const int a_koff = (lane >> 4) << 3;
    const int b_row  = ((lane >> 4) << 3) + (lane & 7);
    const int b_koff = ((lane >> 3) & 1) << 3;

    const int lr = tid >> 2, lc = (tid & 3) << 3;
    const uint32_t so0 = (uint32_t)(lr*SMS + lc) * 2;
    const uint32_t so1 = (uint32_t)((lr+64)*SMS + lc) * 2;

    auto load_stage = [&](int stage, int kb) {
        const int k0 = kb << 5;
        const uint32_t sb = smB + (uint32_t)stage * G_STG * 2;
        const size_t ga0 = (size_t)(m0 + lr) * ND + k0 + lc;
        const size_t ga1 = (size_t)(m0 + lr + 64) * ND + k0 + lc;
        const size_t gb0 = (size_t)(n0 + lr) * ND + k0 + lc;
        const size_t gb1 = (size_t)(n0 + lr + 64) * ND + k0 + lc;
        cp16(sb + 0*G_TILE*2 + so0, Ahi + ga0);
        cp16(sb + 0*G_TILE*2 + so1, Ahi + ga1);
        cp16(sb + 1*G_TILE*2 + so0, Alo + ga0);
        cp16(sb + 1*G_TILE*2 + so1, Alo + ga1);
        cp16(sb + 2*G_TILE*2 + so0, Bhi + gb0);
        cp16(sb + 2*G_TILE*2 + so1, Bhi + gb1);
        cp16(sb + 3*G_TILE*2 + so0, Blo + gb0);
        cp16(sb + 3*G_TILE*2 + so1, Blo + gb1);
        cp_commit();
    };

    load_stage(0, 0);

    for (int kb = 0; kb < 32; kb++) {
        cp_wait<0>();
        __syncthreads();     // stage kb visible; all warps done reading (kb-1)&1
        if (kb + 1 < 32) load_stage((kb + 1) & 1, kb + 1);

        const uint32_t sb = smB + (uint32_t)(kb & 1) * G_STG * 2;
        const uint32_t sAhiB = sb, sAloB = sb + G_TILE*2;
        const uint32_t sBhiB = sb + 2*G_TILE*2, sBloB = sb + 3*G_TILE*2;

        #pragma unroll
        for (int ks = 0; ks < 2; ks++) {
            const int kk = ks << 4;
            uint32_t ah[4][4], al[4][4], bh[4][2], bl[4][2];
            #pragma unroll
            for (int mi = 0; mi < 4; mi++) {
                const uint32_t off =
                    (uint32_t)(((wm + (mi<<4) + a_row)*SMS + kk + a_koff) * 2);
                ldsm4(ah[mi], sAhiB + off);
                ldsm4(al[mi], sAloB + off);
            }
            #pragma unroll
            for (int nj = 0; nj < 2; nj++) {
                const uint32_t off =
                    (uint32_t)(((wn + (nj<<4) + b_row)*SMS + kk + b_koff) * 2);
                uint32_t r4[4];
                ldsm4(r4, sBhiB + off);
                bh[nj*2][0]=r4[0]; bh[nj*2][1]=r4[1];
                bh[nj*2+1][0]=r4[2]; bh[nj*2+1][1]=r4[3];
                ldsm4(r4, sBloB + off);
                bl[nj*2][0]=r4[0]; bl[nj*2][1]=r4[1];
                bl[nj*2+1][0]=r4[2]; bl[nj*2+1][1]=r4[3];
            }
            #pragma unroll
            for (int mi = 0; mi < 4; mi++)
                #pragma unroll
                for (int ni = 0; ni < 4; ni++) {
                    mma_bf16(acc[mi][ni], ah[mi], bh[ni]);
                    mma_bf16(acc[mi][ni], ah[mi], bl[ni]);
                    mma_bf16(acc[mi][ni], al[mi], bh[ni]);
                }
        }
    }

    const int er = lane >> 2, ec = (lane & 3) << 1;
    #pragma unroll
    for (int ni = 0; ni < 4; ni++) {
        const int col = n0 + wn + (ni << 3) + ec;
        const float b0 = __ldg(bias + col), b1 = __ldg(bias + col + 1);
        #pragma unroll
        for (int mi = 0; mi < 4; mi++) {
            const int row = m0 + wm + (mi << 4) + er;
            const float v0 = acc[mi][ni][0] + b0, v1 = acc[mi][ni][1] + b1;
            const float v2 = acc[mi][ni][2] + b0, v3 = acc[mi][ni][3] + b1;
            if (OUTMODE == 0) {
                *(float2*)(C + (size_t)row * ND + col)       = make_float2(v0, v1);
                *(float2*)(C + (size_t)(row + 8) * ND + col) = make_float2(v2, v3);
            } else {
                uint32_t h0 = pk2(v0, v1);
                uint32_t l0 = pk2(v0 - bfl(h0), v1 - bfh(h0));
                uint32_t h1 = pk2(v2, v3);
                uint32_t l1 = pk2(v2 - bfl(h1), v3 - bfh(h1));
                *(uint32_t*)(Chi + (size_t)row * ND + col)       = h0;
                *(uint32_t*)(Clo + (size_t)row * ND + col)       = l0;
                *(uint32_t*)(Chi + (size_t)(row + 8) * ND + col) = h1;
                *(uint32_t*)(Clo + (size_t)(row + 8) * ND + col) = l1;
            }
        }
    }
}

__global__ __launch_bounds__(256, 2) void gemm_qkv(
    const bf16* __restrict__ Ahi, const bf16* __restrict__ Alo,
    const bf16* __restrict__ Whi_base, const bf16* __restrict__ Wlo_base,
    const float* __restrict__ bq, const float* __restrict__ bk,
    const float* __restrict__ bv,
    bf16* __restrict__ qhi, bf16* __restrict__ qlo,
    bf16* __restrict__ khi, bf16* __restrict__ klo,
    bf16* __restrict__ vhi, bf16* __restrict__ vlo)
{
    const int z = blockIdx.z;
    const size_t WSZ = (size_t)ND * ND;
    const bf16* Bhi = Whi_base + (size_t)z * WSZ;
    const bf16* Blo = Wlo_base + (size_t)z * WSZ;
    const float* bias = (z == 0) ? bq : (z == 1) ? bk : bv;
    bf16* Chi = (z == 0) ? qhi : (z == 1) ? khi : vhi;
    bf16* Clo = (z == 0) ? qlo : (z == 1) ? klo : vlo;
    gemm_core<1>(Ahi, Alo, Bhi, Blo, bias, nullptr, Chi, Clo,
                 blockIdx.y << 7, blockIdx.x << 7);
}

__global__ __launch_bounds__(256, 2) void gemm_proj(
    const bf16* __restrict__ Ahi, const bf16* __restrict__ Alo,
    const bf16* __restrict__ Bhi, const bf16* __restrict__ Blo,
    const float* __restrict__ bias, float* __restrict__ C)
{
    gemm_core<0>(Ahi, Alo, Bhi, Blo, bias, C, nullptr, nullptr,
                 blockIdx.y << 7, blockIdx.x << 7);
}

// ---------------------------------------------------------------------------
// Tensor-core flash attention, 2-stage cp.async K/V pipeline (R8 champion,
// measured 551us twice).  Grid: (qtile=16, hb=64).  8 warps; warp = 16 q rows.
// ---------------------------------------------------------------------------
#define APAD 72
#define A_TILE (64*APAD)
#define A_STG  (4*A_TILE)

__global__ __launch_bounds__(256) void attn_mma(
    const bf16* __restrict__ Qhi, const bf16* __restrict__ Qlo,
    const bf16* __restrict__ Khi, const bf16* __restrict__ Klo,
    const bf16* __restrict__ Vhi, const bf16* __restrict__ Vlo,
    bf16* __restrict__ Ohi, bf16* __restrict__ Olo)
{
    extern __shared__ bf16 sm[];
    bf16* sQh = sm;                   // 128 x APAD
    bf16* sQl = sQh + 128*APAD;
    bf16* sKV = sQl + 128*APAD;       // 2 stages x (Kh,Kl,Vh,Vl) 64 x APAD

    const int tid = threadIdx.x;
    const int lane = tid & 31, wid = tid >> 5;
    const int hb = blockIdx.y;
    const int b  = hb & 3, h = hb >> 2;
    const int q0 = blockIdx.x << 7;
    const size_t base = (size_t)b * SEQ * ND + h * HD;

    const uint32_t sKVB = smem_u32(sKV);

    const int kr0 = tid >> 3, kc = (tid & 7) << 3;
    const uint32_t kso0 = (uint32_t)(kr0*APAD + kc) * 2;
    const uint32_t kso1 = (uint32_t)((kr0+32)*APAD + kc) * 2;

    auto load_kv = [&](int stage, int k0) {
        const uint32_t sb = sKVB + (uint32_t)stage * A_STG * 2;
        const size_t g0 = base + (size_t)(k0 + kr0) * ND + kc;
        const size_t g1 = base + (size_t)(k0 + kr0 + 32) * ND + kc;
        cp16(sb + 0*A_TILE*2 + kso0, Khi + g0);
        cp16(sb + 0*A_TILE*2 + kso1, Khi + g1);
        cp16(sb + 1*A_TILE*2 + kso0, Klo + g0);
        cp16(sb + 1*A_TILE*2 + kso1, Klo + g1);
        cp16(sb + 2*A_TILE*2 + kso0, Vhi + g0);
        cp16(sb + 2*A_TILE*2 + kso1, Vhi + g1);
        cp16(sb + 3*A_TILE*2 + kso0, Vlo + g0);
        cp16(sb + 3*A_TILE*2 + kso1, Vlo + g1);
        cp_commit();
    };

    // --- load Q tile (128 x 64 hi/lo) ---
    for (int i = tid; i < 128*8; i += 256) {
        const int r = i >> 3, c8 = (i & 7) << 3;
        const size_t g = base + (size_t)(q0 + r) * ND + c8;
        *(int4*)&sQh[r*APAD + c8] = *(const int4*)(Qhi + g);
        *(int4*)&sQl[r*APAD + c8] = *(const int4*)(Qlo + g);
    }
    load_kv(0, 0);
    __syncthreads();

    // --- Q fragments (hoisted) ---
    const int a_row  = lane & 15;
    const int a_koff = (lane >> 4) << 3;
    uint32_t qh[4][4], ql[4][4];
    #pragma unroll
    for (int ks = 0; ks < 4; ks++) {
        const uint32_t off =
            (uint32_t)(((wid*16 + a_row)*APAD + ks*16 + a_koff) * 2);
        ldsm4(qh[ks], smem_u32(sQh) + off);
        ldsm4(ql[ks], smem_u32(sQl) + off);
    }

    const int b_row  = ((lane >> 4) << 3) + (lane & 7);
    const int b_koff = ((lane >> 3) & 1) << 3;
    const int v_krow = (((lane >> 3) & 1) << 3) + (lane & 7);
    const int v_doff = (lane >> 4) << 3;

    float m0v = -1e30f, m1v = -1e30f, l0v = 0.f, l1v = 0.f;
    float o[8][4] = {};

    for (int kt = 0; kt < 32; kt++) {
        if (kt + 1 < 32) { load_kv((kt + 1) & 1, (kt + 1) << 6); cp_wait<1>(); }
        else             { cp_wait<0>(); }
        __syncthreads();

        const uint32_t sb = sKVB + (uint32_t)(kt & 1) * A_STG * 2;
        const uint32_t sKhB = sb, sKlB = sb + A_TILE*2;
        const uint32_t sVhB = sb + 2*A_TILE*2, sVlB = sb + 3*A_TILE*2;

        // --- S = Q K^T  (16 x 64 per warp) ---
        float s[8][4] = {};
        #pragma unroll
        for (int ks = 0; ks < 4; ks++) {
            #pragma unroll
            for (int ng = 0; ng < 4; ng++) {
                const uint32_t off =
                    (uint32_t)(((ng*16 + b_row)*APAD + ks*16 + b_koff) * 2);
                uint32_t kbh[4], kbl[4];
                ldsm4(kbh, sKhB + off);
                ldsm4(kbl, sKlB + off);
                mma_bf16(s[ng*2],   qh[ks], kbh);
                mma_bf16(s[ng*2+1], qh[ks], kbh + 2);
                mma_bf16(s[ng*2],   qh[ks], kbl);
                mma_bf16(s[ng*2+1], qh[ks], kbl + 2);
                mma_bf16(s[ng*2],   ql[ks], kbh);
                mma_bf16(s[ng*2+1], ql[ks], kbh + 2);
            }
        }

        // --- online softmax ---
        float mx0 = m0v, mx1 = m1v;
        #pragma unroll
        for (int f = 0; f < 8; f++) {
            mx0 = fmaxf(mx0, fmaxf(s[f][0], s[f][1]));
            mx1 = fmaxf(mx1, fmaxf(s[f][2], s[f][3]));
        }
        mx0 = fmaxf(mx0, __shfl_xor_sync(0xffffffffu, mx0, 1));
        mx0 = fmaxf(mx0, __shfl_xor_sync(0xffffffffu, mx0, 2));
        mx1 = fmaxf(mx1, __shfl_xor_sync(0xffffffffu, mx1, 1));
        mx1 = fmaxf(mx1, __shfl_xor_sync(0xffffffffu, mx1, 2));
        const float sc0 = __expf(m0v - mx0);
        const float sc1 = __expf(m1v - mx1);
        float sum0 = 0.f, sum1 = 0.f;
        #pragma unroll
        for (int f = 0; f < 8; f++) {
            s[f][0] = __expf(s[f][0] - mx0);
            s[f][1] = __expf(s[f][1] - mx0);
            s[f][2] = __expf(s[f][2] - mx1);
            s[f][3] = __expf(s[f][3] - mx1);
            sum0 += s[f][0] + s[f][1];
            sum1 += s[f][2] + s[f][3];
        }
        sum0 += __shfl_xor_sync(0xffffffffu, sum0, 1);
        sum0 += __shfl_xor_sync(0xffffffffu, sum0, 2);
        sum1 += __shfl_xor_sync(0xffffffffu, sum1, 1);
        sum1 += __shfl_xor_sync(0xffffffffu, sum1, 2);
        l0v = l0v * sc0 + sum0;  m0v = mx0;
        l1v = l1v * sc1 + sum1;  m1v = mx1;
        #pragma unroll
        for (int f = 0; f < 8; f++) {
            o[f][0] *= sc0; o[f][1] *= sc0;
            o[f][2] *= sc1; o[f][3] *= sc1;
        }

        // --- pack P -> bf16 hi/lo A-fragments ---
        uint32_t ph[4][4], pl[4][4];
        #pragma unroll
        for (int ksp = 0; ksp < 4; ksp++) {
            const float* e = s[2*ksp];
            const float* oq = s[2*ksp+1];
            ph[ksp][0] = pk2(e[0], e[1]);
            pl[ksp][0] = pk2(e[0] - bfl(ph[ksp][0]), e[1] - bfh(ph[ksp][0]));
            ph[ksp][1] = pk2(e[2], e[3]);
            pl[ksp][1] = pk2(e[2] - bfl(ph[ksp][1]), e[3] - bfh(ph[ksp][1]));
            ph[ksp][2] = pk2(oq[0], oq[1]);
            pl[ksp][2] = pk2(oq[0] - bfl(ph[ksp][2]), oq[1] - bfh(ph[ksp][2]));
            ph[ksp][3] = pk2(oq[2], oq[3]);
            pl[ksp][3] = pk2(oq[2] - bfl(ph[ksp][3]), oq[3] - bfh(ph[ksp][3]));
        }

        // --- O += P V ---
        #pragma unroll
        for (int ksp = 0; ksp < 4; ksp++) {
            #pragma unroll
            for (int dg = 0; dg < 4; dg++) {
                const uint32_t off =
                    (uint32_t)(((ksp*16 + v_krow)*APAD + dg*16 + v_doff) * 2);
                uint32_t vbh[4], vbl[4];
                ldsm4t(vbh, sVhB + off);
                ldsm4t(vbl, sVlB + off);
                mma_bf16(o[dg*2],   ph[ksp], vbh);
                mma_bf16(o[dg*2+1], ph[ksp], vbh + 2);
                mma_bf16(o[dg*2],   ph[ksp], vbl);
                mma_bf16(o[dg*2+1], ph[ksp], vbl + 2);
                mma_bf16(o[dg*2],   pl[ksp], vbh);
                mma_bf16(o[dg*2+1], pl[ksp], vbh + 2);
            }
        }
        __syncthreads();
    }

    // --- normalize + write hi/lo bf16 output ---
    const float inv0 = 1.0f / l0v, inv1 = 1.0f / l1v;
    const int r0 = q0 + wid*16 + (lane >> 2);
    const int ec = (lane & 3) << 1;
    #pragma unroll
    for (int dg = 0; dg < 8; dg++) {
        const int col = dg*8 + ec;
        const size_t g0 = base + (size_t)r0 * ND + col;
        const size_t g1 = base + (size_t)(r0 + 8) * ND + col;
        const float v0 = o[dg][0]*inv0, v1 = o[dg][1]*inv0;
        const float v2 = o[dg][2]*inv1, v3 = o[dg][3]*inv1;
        uint32_t h0 = pk2(v0, v1);
        uint32_t l0 = pk2(v0 - bfl(h0), v1 - bfh(h0));
        uint32_t h1 = pk2(v2, v3);
        uint32_t l1 = pk2(v2 - bfl(h1), v3 - bfh(h1));
        *(uint32_t*)(Ohi + g0) = h0;
        *(uint32_t*)(Olo + g0) = l0;
        *(uint32_t*)(Ohi + g1) = h1;
        *(uint32_t*)(Olo + g1) = l1;
    }
}

// ---------------------------------------------------------------------------
extern "C" void kernel_launch(void* const* d_in, const int* in_sizes, int n_in,
                              void* d_out, int out_size)
{
    const float* x  = (const float*)d_in[0];
    const float* Wq = (const float*)d_in[1];
    const float* bq = (const float*)d_in[2];
    const float* Wk = (const float*)d_in[3];
    const float* bk = (const float*)d_in[4];
    const float* Wv = (const float*)d_in[5];
    const float* bv = (const float*)d_in[6];
    const float* Wp = (const float*)d_in[7];
    const float* bp = (const float*)d_in[8];
    float* out = (float*)d_out;

    bf16 *xhi, *xlo, *whi, *wlo;
    bf16 *qhi, *qlo, *khi, *klo, *vhi, *vlo, *ohi, *olo;
    cudaGetSymbolAddress((void**)&xhi, g_xhi);
    cudaGetSymbolAddress((void**)&xlo, g_xlo);
    cudaGetSymbolAddress((void**)&whi, g_whi);
    cudaGetSymbolAddress((void**)&wlo, g_wlo);
    cudaGetSymbolAddress((void**)&qhi, g_qhi);
    cudaGetSymbolAddress((void**)&qlo, g_qlo);
    cudaGetSymbolAddress((void**)&khi, g_khi);
    cudaGetSymbolAddress((void**)&klo, g_klo);
    cudaGetSymbolAddress((void**)&vhi, g_vhi);
    cudaGetSymbolAddress((void**)&vlo, g_vlo);
    cudaGetSymbolAddress((void**)&ohi, g_ohi);
    cudaGetSymbolAddress((void**)&olo, g_olo);

    const size_t WSZ = (size_t)ND * ND;

    split_f32<<<(MTOT*ND/4 + 255)/256, 256>>>(x, xhi, xlo, MTOT*ND/4);
    split_w4<<<dim3((ND*ND/4 + 255)/256, 4), 256>>>(Wq, Wk, Wv, Wp, whi, wlo);

    const int gemm_smem = 2 * G_STG * (int)sizeof(bf16);   // 81,920 B
    cudaFuncSetAttribute(gemm_qkv, cudaFuncAttributeMaxDynamicSharedMemorySize,
                         gemm_smem);
    cudaFuncSetAttribute(gemm_proj, cudaFuncAttributeMaxDynamicSharedMemorySize,
                         gemm_smem);

    gemm_qkv<<<dim3(ND/128, MTOT/128, 3), 256, gemm_smem>>>(
        xhi, xlo, whi, wlo, bq, bk, bv,
        qhi, qlo, khi, klo, vhi, vlo);

    const int attn_smem = (2*128*APAD + 2*A_STG) * (int)sizeof(bf16);  // 110,592 B
    cudaFuncSetAttribute(attn_mma,
                         cudaFuncAttributeMaxDynamicSharedMemorySize, attn_smem);
    attn_mma<<<dim3(SEQ/128, NH*BATCH), 256, attn_smem>>>(
        qhi, qlo, khi, klo, vhi, vlo, ohi, olo);

    gemm_proj<<<dim3(ND/128, MTOT/128), 256, gemm_smem>>>(
        ohi, olo, whi + 3*WSZ, wlo + 3*WSZ, bp, out);
}